// round 5
// baseline (speedup 1.0000x reference)
#include <cuda_runtime.h>

// Bidirectional LSTM, B=16, S=4096, H=F=256.
// 128 persistent CTAs: dir = blockIdx.x>>6, slice = blockIdx.x&63.
// Each CTA owns 4 h-columns (16 z-columns across the 4 gates), keeps Wi/Wh
// slices + c-state in SMEM for the whole scan. Per-step grid-slice barrier
// via atomics; x-projection for the next step overlaps the barrier wait.

#define BB 16
#define SS 4096
#define HH 256
#define FF 256
#define G4 1024        // 4*F
#define NC 16          // z-columns per CTA
#define NSL 64         // slices per direction
#define KPAD 260       // padded K stride (bank-conflict mitigation, 16B aligned)
#define NT 256

__device__ float    g_hbuf[2][2][BB * FF];   // [dir][parity][b*F + col]
__device__ unsigned g_cnt[2];
__device__ unsigned g_gen[2];

__device__ __forceinline__ void fma2(unsigned long long &acc,
                                     unsigned long long a, unsigned long long w) {
    asm("fma.rn.f32x2 %0, %1, %2, %0;" : "+l"(acc) : "l"(a), "l"(w));
}
__device__ __forceinline__ float red2(unsigned long long p) {
    float lo, hi;
    asm("mov.b64 {%0,%1}, %2;" : "=f"(lo), "=f"(hi) : "l"(p));
    return lo + hi;
}
__device__ __forceinline__ float sigm(float x) {
    return 1.0f / (1.0f + __expf(-x));
}
__device__ __forceinline__ float tanh_fast(float x) {
    // (e^{2x}-1)/(e^{2x}+1) rearranged to avoid inf/inf
    return 1.0f - 2.0f / (__expf(2.0f * x) + 1.0f);
}

// dot over K=256 using packed f32x2 FMAs; v and w are 16B-aligned SMEM rows.
__device__ __forceinline__ float dot256(const float* __restrict__ v,
                                        const float* __restrict__ w) {
    unsigned long long a0 = 0ull, a1 = 0ull;
#pragma unroll
    for (int k = 0; k < 256; k += 8) {
        ulonglong2 xv = *reinterpret_cast<const ulonglong2*>(v + k);
        ulonglong2 wv = *reinterpret_cast<const ulonglong2*>(w + k);
        fma2(a0, xv.x, wv.x);
        fma2(a1, xv.y, wv.y);
        ulonglong2 xv2 = *reinterpret_cast<const ulonglong2*>(v + k + 4);
        ulonglong2 wv2 = *reinterpret_cast<const ulonglong2*>(w + k + 4);
        fma2(a0, xv2.x, wv2.x);
        fma2(a1, xv2.y, wv2.y);
    }
    return red2(a0) + red2(a1);
}

__global__ void lstm_init_kernel() {
    if (threadIdx.x < 2) {
        g_cnt[threadIdx.x] = 0u;
        g_gen[threadIdx.x] = 0u;
    }
}

__global__ void __launch_bounds__(NT, 1) lstm_scan_kernel(
    const float* __restrict__ x,      // inputs [B][S][H]
    const float* __restrict__ Wi_fw, const float* __restrict__ Wh_fw,
    const float* __restrict__ b_fw,
    const float* __restrict__ Wi_rv, const float* __restrict__ Wh_rv,
    const float* __restrict__ b_rv,
    float* __restrict__ out, int write_finals)
{
    extern __shared__ float sm[];
    float* wi  = sm;                    // NC*KPAD
    float* wh  = wi + NC * KPAD;        // NC*KPAD
    float* xs  = wh + NC * KPAD;        // BB*KPAD
    float* hs  = xs + BB * KPAD;        // BB*KPAD
    float* zb  = hs + BB * KPAD;        // BB*NC
    float* cst = zb + BB * NC;          // BB*4 (c-state, persistent)

    const int bx  = blockIdx.x;
    const int d   = bx >> 6;
    const int sl  = bx & 63;
    const int tid = threadIdx.x;
    const int bb  = tid >> 4;           // batch 0..15
    const int cc  = tid & 15;           // local z-column 0..15 (gate = cc>>2, hc = cc&3)

    const float* Wi   = d ? Wi_rv : Wi_fw;
    const float* Wh   = d ? Wh_rv : Wh_fw;
    const float* bias = d ? b_rv : b_fw;

    // Stage weight slices: column cg = gate*256 + sl*4 + hc
    for (int i = tid; i < NC * HH; i += NT) {
        int c = i >> 8;
        int k = i & 255;
        int cg = ((c >> 2) << 8) + (sl << 2) + (c & 3);
        wi[c * KPAD + k] = Wi[k * G4 + cg];
        wh[c * KPAD + k] = Wh[k * G4 + cg];
    }
    const int colg = ((cc >> 2) << 8) + (sl << 2) + (cc & 3);
    const float bcc = bias[colg];

    for (int i = tid; i < BB * KPAD; i += NT) hs[i] = 0.0f;  // h0 = 0
    if (tid < 64) cst[tid] = 0.0f;                           // c0 = 0

    // Stage x for step 0
    {
        int s0 = d ? (SS - 1) : 0;
        for (int i = tid; i < BB * HH; i += NT) {
            int b2 = i >> 8, k = i & 255;
            xs[b2 * KPAD + k] = x[((size_t)b2 * SS + s0) * HH + k];
        }
    }
    __syncthreads();

    float accx = bcc + dot256(xs + bb * KPAD, wi + cc * KPAD);

    for (int t = 0; t < SS; ++t) {
        // z = (bias + x@Wi) + h@Wh
        float z = accx + dot256(hs + bb * KPAD, wh + cc * KPAD);
        zb[bb * NC + cc] = z;
        __syncthreads();

        int s_cur = d ? (SS - 1 - t) : t;
        if (tid < 64) {
            int b2 = tid >> 2, hc = tid & 3;
            float zi = zb[b2 * NC + 0 + hc];
            float zf = zb[b2 * NC + 4 + hc];
            float zg = zb[b2 * NC + 8 + hc];
            float zo = zb[b2 * NC + 12 + hc];
            float cp = cst[tid];
            float cn = sigm(zf) * cp + sigm(zi) * tanh_fast(zg);
            float hn = sigm(zo) * tanh_fast(cn);
            cst[tid] = cn;
            int col = (sl << 2) + hc;
            g_hbuf[d][t & 1][b2 * FF + col] = hn;
            out[((size_t)b2 * SS + s_cur) * (2 * FF) + d * FF + col] = hn;
            if (t == SS - 1 && write_finals) {
                size_t base = (size_t)BB * SS * 2 * FF + (size_t)d * 2 * BB * FF;
                out[base + b2 * FF + col]           = cn;  // c_final
                out[base + BB * FF + b2 * FF + col] = hn;  // h_final
            }
            __threadfence();
        }
        __syncthreads();
        if (t == SS - 1) break;

        // Arrive at the per-direction barrier (h slice published above)
        if (tid == 0) {
            unsigned a = atomicAdd(&g_cnt[d], 1u);
            if (a == NSL - 1u) {
                g_cnt[d] = 0u;
                __threadfence();
                atomicAdd(&g_gen[d], 1u);
            }
        }

        // Overlap zone: stage next x and compute its projection while peers arrive
        int s_nxt = d ? (SS - 2 - t) : (t + 1);
        for (int i = tid; i < BB * HH; i += NT) {
            int b2 = i >> 8, k = i & 255;
            xs[b2 * KPAD + k] = x[((size_t)b2 * SS + s_nxt) * HH + k];
        }
        __syncthreads();
        accx = bcc + dot256(xs + bb * KPAD, wi + cc * KPAD);

        // Wait for all 64 slices of this direction
        if (tid == 0) {
            while (*((volatile unsigned*)&g_gen[d]) < (unsigned)(t + 1)) { }
            __threadfence();
        }
        __syncthreads();

        // Gather full h(t) (L1-bypassing loads; other SMs wrote it)
        for (int i = tid; i < BB * FF; i += NT) {
            hs[(i >> 8) * KPAD + (i & 255)] = __ldcg(&g_hbuf[d][t & 1][i]);
        }
        __syncthreads();
    }
}

extern "C" void kernel_launch(void* const* d_in, const int* in_sizes, int n_in,
                              void* d_out, int out_size) {
    const float* x     = (const float*)d_in[0];
    const float* Wi_fw = (const float*)d_in[1];
    const float* Wh_fw = (const float*)d_in[2];
    const float* b_fw  = (const float*)d_in[3];
    const float* Wi_rv = (const float*)d_in[4];
    const float* Wh_rv = (const float*)d_in[5];
    const float* b_rv  = (const float*)d_in[6];
    float* out = (float*)d_out;

    int write_finals = (out_size >= (int)((size_t)BB * SS * 2 * FF + 4 * BB * FF)) ? 1 : 0;

    size_t smem = (size_t)(2 * NC * KPAD + 2 * BB * KPAD + BB * NC + BB * 4) * sizeof(float);
    cudaFuncSetAttribute(lstm_scan_kernel,
                         cudaFuncAttributeMaxDynamicSharedMemorySize, (int)smem);

    lstm_init_kernel<<<1, 32>>>();
    lstm_scan_kernel<<<2 * NSL, NT, smem>>>(x, Wi_fw, Wh_fw, b_fw,
                                            Wi_rv, Wh_rv, b_rv, out, write_finals);
}

// round 6
// speedup vs baseline: 1.7949x; 1.7949x over previous
#include <cuda_runtime.h>

// Bidirectional LSTM, B=16, S=4096, H=F=256.
// 128 persistent CTAs: dir = blockIdx.x>>6, slice = blockIdx.x&63.
// Each CTA owns 4 h-columns -> 16 z-columns. Wh/Wi column slices live in
// REGISTERS (packed f32x2) for the whole scan; activations are read from an
// interleaved SMEM layout so each LDS.128 touches only 64B unique (broadcast).
// Warp layout: 8 cols x 4 k-chunks; warp-pair p handles batches 4p..4p+3.
// Per-direction grid barrier via atomics; x-projection overlaps the wait.

#define BB 16
#define SS 4096
#define HH 256
#define FF 256
#define G4 1024
#define NSL 64
#define NT 256

__device__ float    g_hbuf[2][2][BB * FF];   // [dir][parity][b*F + col]
__device__ unsigned g_cnt[2];
__device__ unsigned g_gen[2];

__device__ __forceinline__ void fma2(unsigned long long &acc,
                                     unsigned long long a, unsigned long long w) {
    asm("fma.rn.f32x2 %0, %1, %2, %0;" : "+l"(acc) : "l"(a), "l"(w));
}
__device__ __forceinline__ unsigned long long pk2(float lo, float hi) {
    unsigned long long r;
    asm("mov.b64 %0, {%1,%2};" : "=l"(r) : "f"(lo), "f"(hi));
    return r;
}
__device__ __forceinline__ float red2(unsigned long long p) {
    float lo, hi;
    asm("mov.b64 {%0,%1}, %2;" : "=f"(lo), "=f"(hi) : "l"(p));
    return lo + hi;
}
__device__ __forceinline__ float sigm(float x) {
    return 1.0f / (1.0f + __expf(-x));
}
__device__ __forceinline__ float tanh_fast(float x) {
    return 1.0f - 2.0f / (__expf(2.0f * x) + 1.0f);
}

__global__ void lstm_init_kernel() {
    if (threadIdx.x < 2) {
        g_cnt[threadIdx.x] = 0u;
        g_gen[threadIdx.x] = 0u;
    }
}

__global__ void __launch_bounds__(NT, 1) lstm_scan_kernel(
    const float* __restrict__ x,
    const float* __restrict__ Wi_fw, const float* __restrict__ Wh_fw,
    const float* __restrict__ b_fw,
    const float* __restrict__ Wi_rv, const float* __restrict__ Wh_rv,
    const float* __restrict__ b_rv,
    float* __restrict__ out, int write_finals)
{
    // Interleaved activation layout: 16B chunk index (b*16 + j4)*4 + kc
    //   float offset = b*256 + j4*16 + kc*4, covering k = kc*64 + j4*4 .. +3
    __shared__ __align__(16) float xs[BB * HH];   // 16 KB
    __shared__ __align__(16) float hs[BB * FF];   // 16 KB
    __shared__ float zb[BB * 16];
    __shared__ float cst[64];

    const int bx   = blockIdx.x;
    const int d    = bx >> 6;
    const int sl   = bx & 63;
    const int tid  = threadIdx.x;
    const int w    = tid >> 5;
    const int lane = tid & 31;
    const int p    = w >> 1;            // warp pair: batches 4p..4p+3
    const int half = w & 1;             // which 8 of the 16 cols
    const int col8 = lane & 7;
    const int kc   = lane >> 3;         // k-chunk 0..3 (64 k each)
    const int cc   = (half << 3) + col8;            // local z-col 0..15
    const int colg = ((cc >> 2) << 8) + (sl << 2) + (cc & 3);

    const float* Wi = d ? Wi_rv : Wi_fw;
    const float* Wh = d ? Wh_rv : Wh_fw;
    const float bcc = (d ? b_rv : b_fw)[colg];

    // Cache this thread's weight slice in registers, pre-packed for f32x2.
    unsigned long long wh2[32], wi2[32];
#pragma unroll
    for (int j = 0; j < 32; ++j) {
        int k = (kc << 6) + (j << 1);
        wh2[j] = pk2(Wh[(size_t)k * G4 + colg], Wh[(size_t)(k + 1) * G4 + colg]);
        wi2[j] = pk2(Wi[(size_t)k * G4 + colg], Wi[(size_t)(k + 1) * G4 + colg]);
    }

    for (int i = tid; i < BB * FF; i += NT) hs[i] = 0.0f;   // h0 = 0
    if (tid < 64) cst[tid] = 0.0f;                          // c0 = 0

    // Stage x for step 0 (dest chunk index == idx by construction)
    {
        int s0 = d ? (SS - 1) : 0;
#pragma unroll
        for (int r = 0; r < 4; ++r) {
            int idx = tid + r * NT;
            int kcc = idx & 3, j4 = (idx >> 2) & 15, b = idx >> 6;
            *(float4*)(xs + idx * 4) =
                *(const float4*)(x + ((size_t)b * SS + s0) * HH + kcc * 64 + j4 * 4);
        }
    }
    __syncthreads();

    // Initial x-projection (step 0)
    float accx[4];
#pragma unroll
    for (int i = 0; i < 4; ++i) {
        int b = (p << 2) + i;
        const float* vp = xs + (b << 8) + (kc << 2);
        unsigned long long a0 = 0ull, a1 = 0ull;
#pragma unroll
        for (int j = 0; j < 16; ++j) {
            ulonglong2 v = *(const ulonglong2*)(vp + (j << 4));
            fma2(a0, v.x, wi2[2 * j]);
            fma2(a1, v.y, wi2[2 * j + 1]);
        }
        float s = red2(a0) + red2(a1);
        s += __shfl_xor_sync(0xffffffffu, s, 8);
        s += __shfl_xor_sync(0xffffffffu, s, 16);
        accx[i] = bcc + s;
    }
    __syncthreads();   // xs reads done; loop below overwrites it

    for (int t = 0; t < SS; ++t) {
        // Prefetch+stage x(t+1) now; LDG latency hides under the h-dot.
        if (t < SS - 1) {
            int sn = d ? (SS - 2 - t) : (t + 1);
#pragma unroll
            for (int r = 0; r < 4; ++r) {
                int idx = tid + r * NT;
                int kcc = idx & 3, j4 = (idx >> 2) & 15, b = idx >> 6;
                *(float4*)(xs + idx * 4) =
                    *(const float4*)(x + ((size_t)b * SS + sn) * HH + kcc * 64 + j4 * 4);
            }
        }

        // h-dot: z = accx + h(t-1) @ Wh[:, colg]
#pragma unroll
        for (int i = 0; i < 4; ++i) {
            int b = (p << 2) + i;
            const float* vp = hs + (b << 8) + (kc << 2);
            unsigned long long a0 = 0ull, a1 = 0ull;
#pragma unroll
            for (int j = 0; j < 16; ++j) {
                ulonglong2 v = *(const ulonglong2*)(vp + (j << 4));
                fma2(a0, v.x, wh2[2 * j]);
                fma2(a1, v.y, wh2[2 * j + 1]);
            }
            float s = red2(a0) + red2(a1);
            s += __shfl_xor_sync(0xffffffffu, s, 8);
            s += __shfl_xor_sync(0xffffffffu, s, 16);
            if (lane < 8) zb[(b << 4) + cc] = accx[i] + s;
        }
        __syncthreads();

        // Gate epilogue + publish h
        int s_cur = d ? (SS - 1 - t) : t;
        if (tid < 64) {
            int b2 = tid >> 2, hc = tid & 3;
            float zi = zb[(b2 << 4) + 0  + hc];
            float zf = zb[(b2 << 4) + 4  + hc];
            float zg = zb[(b2 << 4) + 8  + hc];
            float zo = zb[(b2 << 4) + 12 + hc];
            float cp = cst[tid];
            float cn = sigm(zf) * cp + sigm(zi) * tanh_fast(zg);
            float hn = sigm(zo) * tanh_fast(cn);
            cst[tid] = cn;
            int col = (sl << 2) + hc;
            g_hbuf[d][t & 1][(b2 << 8) + col] = hn;
            out[((size_t)b2 * SS + s_cur) * (2 * FF) + d * FF + col] = hn;
            if (t == SS - 1 && write_finals) {
                size_t base = (size_t)BB * SS * 2 * FF + (size_t)d * 2 * BB * FF;
                out[base + b2 * FF + col]           = cn;  // c_final
                out[base + BB * FF + b2 * FF + col] = hn;  // h_final
            }
            __threadfence();
        }
        __syncthreads();
        if (t == SS - 1) break;

        // Arrive at the per-direction barrier
        if (tid == 0) {
            unsigned a = atomicAdd(&g_cnt[d], 1u);
            if (a == NSL - 1u) {
                g_cnt[d] = 0u;
                __threadfence();
                atomicAdd(&g_gen[d], 1u);
            }
        }

        // Overlap zone: x-projection for step t+1 (xs staged above, synced)
#pragma unroll
        for (int i = 0; i < 4; ++i) {
            int b = (p << 2) + i;
            const float* vp = xs + (b << 8) + (kc << 2);
            unsigned long long a0 = 0ull, a1 = 0ull;
#pragma unroll
            for (int j = 0; j < 16; ++j) {
                ulonglong2 v = *(const ulonglong2*)(vp + (j << 4));
                fma2(a0, v.x, wi2[2 * j]);
                fma2(a1, v.y, wi2[2 * j + 1]);
            }
            float s = red2(a0) + red2(a1);
            s += __shfl_xor_sync(0xffffffffu, s, 8);
            s += __shfl_xor_sync(0xffffffffu, s, 16);
            accx[i] = bcc + s;
        }

        // Wait for all 64 slices of this direction
        if (tid == 0) {
            while (*((volatile unsigned*)&g_gen[d]) < (unsigned)(t + 1)) { }
            __threadfence();
        }
        __syncthreads();

        // Gather full h(t) into interleaved hs (L1-bypassing loads)
#pragma unroll
        for (int r = 0; r < 4; ++r) {
            int idx = tid + r * NT;
            int kcc = idx & 3, j4 = (idx >> 2) & 15, b = idx >> 6;
            float4 hv = __ldcg((const float4*)(&g_hbuf[d][t & 1][(b << 8) + kcc * 64 + j4 * 4]));
            *(float4*)(hs + idx * 4) = hv;
        }
        __syncthreads();
    }
}

extern "C" void kernel_launch(void* const* d_in, const int* in_sizes, int n_in,
                              void* d_out, int out_size) {
    const float* x     = (const float*)d_in[0];
    const float* Wi_fw = (const float*)d_in[1];
    const float* Wh_fw = (const float*)d_in[2];
    const float* b_fw  = (const float*)d_in[3];
    const float* Wi_rv = (const float*)d_in[4];
    const float* Wh_rv = (const float*)d_in[5];
    const float* b_rv  = (const float*)d_in[6];
    float* out = (float*)d_out;

    int write_finals = (out_size >= (int)((size_t)BB * SS * 2 * FF + 4 * BB * FF)) ? 1 : 0;

    lstm_init_kernel<<<1, 32>>>();
    lstm_scan_kernel<<<2 * NSL, NT>>>(x, Wi_fw, Wh_fw, b_fw,
                                      Wi_rv, Wh_rv, b_rv, out, write_finals);
}